// round 11
// baseline (speedup 1.0000x reference)
#include <cuda_runtime.h>

// Circuit_87634512707722 — batched 3-qubit statevector:
//   H(q0), H(q1), RX(theta0)(q0), RX(theta1)(q1), CNOT(ctrl=q0, tgt=q2)
// Fused per qubit: U_q = RX(theta_q)·H = [[a-ib, a+ib],[a-ib, -(a+ib)]],
//   a = cos(theta/2)/√2, b = sin(theta/2)/√2.
//
// FINAL — plateau triple-confirmed (R2/R8/R10 all 43.52us harness).
// 268 MB app traffic in ~35.6us kernel = 7.5 TB/s effective (94% of spec).
// Falsified levers: streaming hints (R3/R4: -1.4us), evict-last (R6: no-op),
// per-thread MLP (R3: regression), persistent 1-wave (R7: -5.7us via occ),
// 256-bit ld/st (R6: neutral), block=512 (R9: neutral-).
//
// Quarter-state lane mapping for perfect coalescing:
//   warp w covers 16 states. lane l owns amps {2(l&3), 2(l&3)+1} of
//   state (16w + (l>>2)) and state (16w + 8 + (l>>2)).
//   amp bit2 (q0) == lane bit1  -> exchange via shfl_xor(2)
//   amp bit1 (q1) == lane bit0  -> exchange via shfl_xor(1)
//   amp bit0 (q2) in-thread     -> CNOT = local swap when q0 half is 1
// All loads:  LDG.64  xr2[64w+l], xr2[64w+32+l] (contiguous 256B/warp)
// All stores: STG.128 out4[64w+l], out4[64w+32+l] (contiguous 512B/warp)

#define BQ 2097152
#define NTHREADS (2 * BQ)   // 2 threads per state (quarter-state each, 2 states/thread)

__device__ __forceinline__ void gate_round(float a, float bs, float sz, int xorm,
                                           float& x0r, float& x0i,
                                           float& x1r, float& x1i) {
    // z = (a - i*bs) * x  (bs carries the per-half sign; sz = combine sign)
    float z0r = fmaf(a, x0r,  bs * x0i);
    float z0i = fmaf(a, x0i, -bs * x0r);
    float z1r = fmaf(a, x1r,  bs * x1i);
    float z1i = fmaf(a, x1i, -bs * x1r);
    float w0r = __shfl_xor_sync(0xffffffffu, z0r, xorm);
    float w0i = __shfl_xor_sync(0xffffffffu, z0i, xorm);
    float w1r = __shfl_xor_sync(0xffffffffu, z1r, xorm);
    float w1i = __shfl_xor_sync(0xffffffffu, z1i, xorm);
    // half0: y = z + w ; half1: y = w - z
    x0r = fmaf(sz, z0r, w0r);
    x0i = fmaf(sz, z0i, w0i);
    x1r = fmaf(sz, z1r, w1r);
    x1i = fmaf(sz, z1i, w1i);
}

__global__ __launch_bounds__(256)
void circuit_kernel(const float2* __restrict__ xr2,
                    const float2* __restrict__ xi2,
                    const float* __restrict__ theta,
                    float4* __restrict__ out4) {
    int t = blockIdx.x * blockDim.x + threadIdx.x;
    int l = t & 31;
    int base = ((t >> 5) << 6) + l;   // float2-index for loads AND float4-index for stores

    // Front-batch all 4 coalesced loads (MLP=4)
    float2 ra  = xr2[base];
    float2 rb  = xr2[base + 32];
    float2 ia  = xi2[base];
    float2 ib_ = xi2[base + 32];

    // Gate constants (uniform; MUFU hidden under LDG latency)
    float t0 = theta[0] * 0.5f;
    float t1 = theta[1] * 0.5f;
    const float is2 = 0.70710678118654752f;
    float s0, c0, s1, c1;
    __sincosf(t0, &s0, &c0);
    __sincosf(t1, &s1, &c1);
    float a0 = c0 * is2, b0 = s0 * is2;
    float a1 = c1 * is2, b1 = s1 * is2;

    int h0 = (l >> 1) & 1;   // this lane's q0 bit value
    int h1 = l & 1;          // this lane's q1 bit value
    float bs0 = h0 ? -b0 : b0;
    float sz0 = h0 ? -1.0f : 1.0f;
    float bs1 = h1 ? -b1 : b1;
    float sz1 = h1 ? -1.0f : 1.0f;

    // State A amps: x0=(ra.x, ia.x), x1=(ra.y, ia.y); state B likewise.
    // Qubit 0 gate (partner lane l^2)
    gate_round(a0, bs0, sz0, 2, ra.x, ia.x,  ra.y, ia.y);
    gate_round(a0, bs0, sz0, 2, rb.x, ib_.x, rb.y, ib_.y);
    // Qubit 1 gate (partner lane l^1)
    gate_round(a1, bs1, sz1, 1, ra.x, ia.x,  ra.y, ia.y);
    gate_round(a1, bs1, sz1, 1, rb.x, ib_.x, rb.y, ib_.y);

    // CNOT(ctrl=q0, tgt=q2): lanes with q0==1 swap their local amp pair (bit0 flip)
    float A0r = h0 ? ra.y  : ra.x;
    float A0i = h0 ? ia.y  : ia.x;
    float A1r = h0 ? ra.x  : ra.y;
    float A1i = h0 ? ia.x  : ia.y;
    float B0r = h0 ? rb.y  : rb.x;
    float B0i = h0 ? ib_.y : ib_.x;
    float B1r = h0 ? rb.x  : rb.y;
    float B1i = h0 ? ib_.x : ib_.y;

    // Interleaved (re,im) output chunks, fully coalesced stores
    out4[base]      = make_float4(A0r, A0i, A1r, A1i);
    out4[base + 32] = make_float4(B0r, B0i, B1r, B1i);
}

extern "C" void kernel_launch(void* const* d_in, const int* in_sizes, int n_in,
                              void* d_out, int out_size) {
    const float2* xr = (const float2*)d_in[0];
    const float2* xi = (const float2*)d_in[1];
    const float*  th = (const float*)d_in[2];
    // d_in[3] = angle, dead argument

    float4* out = (float4*)d_out;

    const int threads = 256;
    const int blocks = NTHREADS / threads;   // 16384, exact
    circuit_kernel<<<blocks, threads>>>(xr, xi, th, out);
}

// round 12
// speedup vs baseline: 1.0228x; 1.0228x over previous
#include <cuda_runtime.h>

// Circuit_87634512707722 — batched 3-qubit statevector:
//   H(q0), H(q1), RX(theta0)(q0), RX(theta1)(q1), CNOT(ctrl=q0, tgt=q2)
// Fused per qubit: U_q = RX(theta_q)·H, a = cos(th/2)/√2, b = sin(th/2)/√2.
//
// R12: last untested A/B cell — R3's 4-states-per-thread structure with
// PLAIN loads/stores (no cache hints). R3 measured 36.4us WITH ldcs/stcs;
// R4 showed stcs alone costs ~+1.4us on the 2-state config. If that cost
// transfers, this cell lands ~35.0us (vs best 35.6). Same quarter-state
// shfl mapping and perfect coalescing as R2.
//
//   lane l owns amps {2(l&3), 2(l&3)+1}; amp bit2 (q0) = lane bit1
//   (shfl_xor 2), amp bit1 (q1) = lane bit0 (shfl_xor 1), amp bit0 (q2)
//   in-thread (CNOT = local swap).
// Loads:  8x LDG.64, each contiguous 256B/warp.  Stores: 4x STG.128,
// each contiguous 512B/warp. All default cache policy.

#define BQ 2097152
#define NTHREADS (BQ)   // 4 states per thread (quarter-state each)

__device__ __forceinline__ void gate_round(float a, float bs, float sz, int xorm,
                                           float& x0r, float& x0i,
                                           float& x1r, float& x1i) {
    // z = (a - i*bs) * x  (bs carries the per-half sign; sz = combine sign)
    float z0r = fmaf(a, x0r,  bs * x0i);
    float z0i = fmaf(a, x0i, -bs * x0r);
    float z1r = fmaf(a, x1r,  bs * x1i);
    float z1i = fmaf(a, x1i, -bs * x1r);
    float w0r = __shfl_xor_sync(0xffffffffu, z0r, xorm);
    float w0i = __shfl_xor_sync(0xffffffffu, z0i, xorm);
    float w1r = __shfl_xor_sync(0xffffffffu, z1r, xorm);
    float w1i = __shfl_xor_sync(0xffffffffu, z1i, xorm);
    // half0: y = z + w ; half1: y = w - z
    x0r = fmaf(sz, z0r, w0r);
    x0i = fmaf(sz, z0i, w0i);
    x1r = fmaf(sz, z1r, w1r);
    x1i = fmaf(sz, z1i, w1i);
}

__global__ __launch_bounds__(256)
void circuit_kernel(const float2* __restrict__ xr2,
                    const float2* __restrict__ xi2,
                    const float* __restrict__ theta,
                    float4* __restrict__ out4) {
    int t = blockIdx.x * blockDim.x + threadIdx.x;
    int l = t & 31;
    int base = ((t >> 5) << 7) + l;   // warp covers 32 states = 128 float2/float4 slots

    // Front-batch all 8 coalesced loads (MLP=8), default policy
    float2 r0 = xr2[base];
    float2 r1 = xr2[base + 32];
    float2 r2 = xr2[base + 64];
    float2 r3 = xr2[base + 96];
    float2 i0 = xi2[base];
    float2 i1 = xi2[base + 32];
    float2 i2 = xi2[base + 64];
    float2 i3 = xi2[base + 96];

    // Gate constants (uniform; MUFU hidden under LDG latency)
    float t0 = theta[0] * 0.5f;
    float t1 = theta[1] * 0.5f;
    const float is2 = 0.70710678118654752f;
    float s0, c0, s1, c1;
    __sincosf(t0, &s0, &c0);
    __sincosf(t1, &s1, &c1);
    float a0 = c0 * is2, b0 = s0 * is2;
    float a1 = c1 * is2, b1 = s1 * is2;

    int h0 = (l >> 1) & 1;   // this lane's q0 bit value
    int h1 = l & 1;          // this lane's q1 bit value
    float bs0 = h0 ? -b0 : b0;
    float sz0 = h0 ? -1.0f : 1.0f;
    float bs1 = h1 ? -b1 : b1;
    float sz1 = h1 ? -1.0f : 1.0f;

    // Qubit 0 gate (partner lane l^2)
    gate_round(a0, bs0, sz0, 2, r0.x, i0.x, r0.y, i0.y);
    gate_round(a0, bs0, sz0, 2, r1.x, i1.x, r1.y, i1.y);
    gate_round(a0, bs0, sz0, 2, r2.x, i2.x, r2.y, i2.y);
    gate_round(a0, bs0, sz0, 2, r3.x, i3.x, r3.y, i3.y);
    // Qubit 1 gate (partner lane l^1)
    gate_round(a1, bs1, sz1, 1, r0.x, i0.x, r0.y, i0.y);
    gate_round(a1, bs1, sz1, 1, r1.x, i1.x, r1.y, i1.y);
    gate_round(a1, bs1, sz1, 1, r2.x, i2.x, r2.y, i2.y);
    gate_round(a1, bs1, sz1, 1, r3.x, i3.x, r3.y, i3.y);

    // CNOT(ctrl=q0, tgt=q2): lanes with q0==1 swap their local amp pair.
    // Fold into interleaved (re,im) stores; fully coalesced default STG.128.
    out4[base]      = h0 ? make_float4(r0.y, i0.y, r0.x, i0.x)
                         : make_float4(r0.x, i0.x, r0.y, i0.y);
    out4[base + 32] = h0 ? make_float4(r1.y, i1.y, r1.x, i1.x)
                         : make_float4(r1.x, i1.x, r1.y, i1.y);
    out4[base + 64] = h0 ? make_float4(r2.y, i2.y, r2.x, i2.x)
                         : make_float4(r2.x, i2.x, r2.y, i2.y);
    out4[base + 96] = h0 ? make_float4(r3.y, i3.y, r3.x, i3.x)
                         : make_float4(r3.x, i3.x, r3.y, i3.y);
}

extern "C" void kernel_launch(void* const* d_in, const int* in_sizes, int n_in,
                              void* d_out, int out_size) {
    const float2* xr = (const float2*)d_in[0];
    const float2* xi = (const float2*)d_in[1];
    const float*  th = (const float*)d_in[2];
    // d_in[3] = angle, dead argument

    float4* out = (float4*)d_out;

    const int threads = 256;
    const int blocks = NTHREADS / threads;   // 8192, exact
    circuit_kernel<<<blocks, threads>>>(xr, xi, th, out);
}